// round 4
// baseline (speedup 1.0000x reference)
#include <cuda_runtime.h>

// Problem constants (shapes fixed by the reference).
#define B_SZ   32768
#define D_SZ   128
#define H_SZ   64
#define G_SZ   256      // 4*H
#define NSTEP  32
#define ROWS   64       // batch rows per CTA
#define NTHR   256
#define NCTA   (B_SZ / ROWS)   // 512

// K-major transposed weights, shared by all CTAs (read-only after prologue).
// W0t: [192][256]  rows 0..127 = Wih0^T, rows 128..191 = Whh0^T
// W1t: [128][256]  rows 0..63  = Wih1^T, rows 64..127  = Whh1^T
// Wfct:[64][128]   = Wfc^T
__device__ __align__(16) float g_W0t[192 * 256];
__device__ __align__(16) float g_W1t[128 * 256];
__device__ __align__(16) float g_Wfct[64 * 128];

__global__ void transpose_weights(const float* __restrict__ Wih0,
                                  const float* __restrict__ Whh0,
                                  const float* __restrict__ Wih1,
                                  const float* __restrict__ Whh1,
                                  const float* __restrict__ Wfc)
{
    int i = blockIdx.x * blockDim.x + threadIdx.x;
    const int S0 = 192 * 256;
    const int S1 = S0 + 128 * 256;
    const int S2 = S1 + 64 * 128;
    if (i < S0) {
        int k = i >> 8, n = i & 255;
        g_W0t[i] = (k < 128) ? Wih0[n * 128 + k] : Whh0[n * 64 + (k - 128)];
    } else if (i < S1) {
        int ii = i - S0;
        int k = ii >> 8, n = ii & 255;
        g_W1t[ii] = (k < 64) ? Wih1[n * 64 + k] : Whh1[n * 64 + (k - 64)];
    } else if (i < S2) {
        int ii = i - S1;
        int k = ii >> 7, n = ii & 127;
        g_Wfct[ii] = Wfc[n * 64 + k];
    }
}

__device__ __forceinline__ float sigf(float x) {
    return __fdividef(1.0f, 1.0f + __expf(-x));
}
// tanh(x) = 2*sigmoid(2x) - 1 ; absolute error ~1e-7, fine at these magnitudes.
__device__ __forceinline__ float tanhfast(float x) {
    return __fdividef(2.0f, 1.0f + __expf(-2.0f * x)) - 1.0f;
}

// C[64 x 256] += A[64 x K] * Wt[K x 256]
// Warp w owns rows w*8..w*8+7 (A loads are warp-broadcast LDS.128).
// Lane ln owns cols {ln*4+e} and {128+ln*4+e} (coalesced 512B LDG.128 per warp).
template <int K, int LDA>
__device__ __forceinline__ void gemm256(float acc[8][8],
                                        const float* __restrict__ As,
                                        const float* __restrict__ Wt,
                                        int w, int ln)
{
#pragma unroll 1
    for (int kk = 0; kk < K; kk += 4) {
        float a[8][4];
#pragma unroll
        for (int m = 0; m < 8; ++m) {
            float4 t = *(const float4*)(As + (w * 8 + m) * LDA + kk);
            a[m][0] = t.x; a[m][1] = t.y; a[m][2] = t.z; a[m][3] = t.w;
        }
        float b[4][8];
#pragma unroll
        for (int e = 0; e < 4; ++e) {
            float4 t0 = *(const float4*)(Wt + (kk + e) * 256 + ln * 4);
            float4 t1 = *(const float4*)(Wt + (kk + e) * 256 + 128 + ln * 4);
            b[e][0] = t0.x; b[e][1] = t0.y; b[e][2] = t0.z; b[e][3] = t0.w;
            b[e][4] = t1.x; b[e][5] = t1.y; b[e][6] = t1.z; b[e][7] = t1.w;
        }
#pragma unroll
        for (int m = 0; m < 8; ++m)
#pragma unroll
            for (int e = 0; e < 4; ++e)
#pragma unroll
                for (int j = 0; j < 8; ++j)
                    acc[m][j] = fmaf(a[m][e], b[e][j], acc[m][j]);
    }
}

// C[64 x 128] += A[64 x K] * Wt[K x 128]   (fc projection)
template <int K, int LDA>
__device__ __forceinline__ void gemm128(float acc[8][4],
                                        const float* __restrict__ As,
                                        const float* __restrict__ Wt,
                                        int w, int ln)
{
#pragma unroll 1
    for (int kk = 0; kk < K; kk += 4) {
        float a[8][4];
#pragma unroll
        for (int m = 0; m < 8; ++m) {
            float4 t = *(const float4*)(As + (w * 8 + m) * LDA + kk);
            a[m][0] = t.x; a[m][1] = t.y; a[m][2] = t.z; a[m][3] = t.w;
        }
        float b[4][4];
#pragma unroll
        for (int e = 0; e < 4; ++e) {
            float4 t0 = *(const float4*)(Wt + (kk + e) * 128 + ln * 4);
            b[e][0] = t0.x; b[e][1] = t0.y; b[e][2] = t0.z; b[e][3] = t0.w;
        }
#pragma unroll
        for (int m = 0; m < 8; ++m)
#pragma unroll
            for (int e = 0; e < 4; ++e)
#pragma unroll
                for (int j = 0; j < 4; ++j)
                    acc[m][j] = fmaf(a[m][e], b[e][j], acc[m][j]);
    }
}

// SMEM layout (floats): inp[64*128] | h0[64*64] | h1[64*64] | gates[64*256]
#define SM_INP 0
#define SM_H0  (64 * 128)
#define SM_H1  (SM_H0 + 64 * 64)
#define SM_G   (SM_H1 + 64 * 64)
#define SM_FLOATS (SM_G + 64 * 256)   // 32768 floats = 128 KB

__global__ __launch_bounds__(NTHR) void lstm_kernel(
    const float* __restrict__ x,
    const float* __restrict__ b0,
    const float* __restrict__ b1,
    const float* __restrict__ bfc,
    float* __restrict__ out)
{
    extern __shared__ float sm[];
    float* s_inp = sm + SM_INP;
    float* s_h0  = sm + SM_H0;
    float* s_h1  = sm + SM_H1;
    float* s_g   = sm + SM_G;

    const int tid = threadIdx.x;
    const int w   = tid >> 5;    // warp id 0..7 -> row group
    const int ln  = tid & 31;    // lane -> col group
    const int rowg0 = blockIdx.x * ROWS;

    // Stage this CTA's x tile into SMEM (coalesced float4).
#pragma unroll 1
    for (int idx = tid; idx < 64 * 32; idx += NTHR) {
        int r = idx >> 5, c = (idx & 31) << 2;
        *(float4*)(s_inp + r * 128 + c) =
            *(const float4*)(x + (size_t)(rowg0 + r) * 128 + c);
    }
#pragma unroll 1
    for (int idx = tid; idx < 64 * 64; idx += NTHR) {
        s_h0[idx] = 0.0f;
        s_h1[idx] = 0.0f;
    }

    // Per-thread bias fragments (match GEMM col ownership).
    float b0v[8], b1v[8], bfcv[4];
    {
        float4 t;
        t = *(const float4*)(b0 + ln * 4);
        b0v[0] = t.x; b0v[1] = t.y; b0v[2] = t.z; b0v[3] = t.w;
        t = *(const float4*)(b0 + 128 + ln * 4);
        b0v[4] = t.x; b0v[5] = t.y; b0v[6] = t.z; b0v[7] = t.w;
        t = *(const float4*)(b1 + ln * 4);
        b1v[0] = t.x; b1v[1] = t.y; b1v[2] = t.z; b1v[3] = t.w;
        t = *(const float4*)(b1 + 128 + ln * 4);
        b1v[4] = t.x; b1v[5] = t.y; b1v[6] = t.z; b1v[7] = t.w;
        t = *(const float4*)(bfc + ln * 4);
        bfcv[0] = t.x; bfcv[1] = t.y; bfcv[2] = t.z; bfcv[3] = t.w;
    }

    // Cell-state registers: thread owns hidden col jc, rows rt*16..rt*16+15.
    float c0r[16], c1r[16];
#pragma unroll
    for (int i = 0; i < 16; ++i) { c0r[i] = 0.0f; c1r[i] = 0.0f; }
    const int jc = tid & 63;
    const int rt = tid >> 6;

    __syncthreads();

#pragma unroll 1
    for (int t = 0; t < NSTEP; ++t) {
        // ---------- layer 0 gates: inp @ Wih0^T + h0 @ Whh0^T + b0 ----------
        {
            float acc[8][8];
#pragma unroll
            for (int m = 0; m < 8; ++m)
#pragma unroll
                for (int j = 0; j < 8; ++j) acc[m][j] = b0v[j];
            gemm256<128, 128>(acc, s_inp, g_W0t, w, ln);
            gemm256<64, 64>(acc, s_h0, g_W0t + 128 * 256, w, ln);
#pragma unroll
            for (int m = 0; m < 8; ++m) {
                int row = w * 8 + m;
                *(float4*)(s_g + row * 256 + ln * 4) =
                    make_float4(acc[m][0], acc[m][1], acc[m][2], acc[m][3]);
                *(float4*)(s_g + row * 256 + 128 + ln * 4) =
                    make_float4(acc[m][4], acc[m][5], acc[m][6], acc[m][7]);
            }
        }
        __syncthreads();

        // ---------- cell 0 ----------
#pragma unroll
        for (int i = 0; i < 16; ++i) {
            int r = rt * 16 + i;
            const float* gr = s_g + r * 256 + jc;
            float c = sigf(gr[64]) * c0r[i] + sigf(gr[0]) * tanhfast(gr[128]);
            c0r[i] = c;
            s_h0[r * 64 + jc] = sigf(gr[192]) * tanhfast(c);
        }
        __syncthreads();

        // ---------- layer 1 gates: h0 @ Wih1^T + h1 @ Whh1^T + b1 ----------
        {
            float acc[8][8];
#pragma unroll
            for (int m = 0; m < 8; ++m)
#pragma unroll
                for (int j = 0; j < 8; ++j) acc[m][j] = b1v[j];
            gemm256<64, 64>(acc, s_h0, g_W1t, w, ln);
            gemm256<64, 64>(acc, s_h1, g_W1t + 64 * 256, w, ln);
#pragma unroll
            for (int m = 0; m < 8; ++m) {
                int row = w * 8 + m;
                *(float4*)(s_g + row * 256 + ln * 4) =
                    make_float4(acc[m][0], acc[m][1], acc[m][2], acc[m][3]);
                *(float4*)(s_g + row * 256 + 128 + ln * 4) =
                    make_float4(acc[m][4], acc[m][5], acc[m][6], acc[m][7]);
            }
        }
        __syncthreads();

        // ---------- cell 1 ----------
#pragma unroll
        for (int i = 0; i < 16; ++i) {
            int r = rt * 16 + i;
            const float* gr = s_g + r * 256 + jc;
            float c = sigf(gr[64]) * c1r[i] + sigf(gr[0]) * tanhfast(gr[128]);
            c1r[i] = c;
            s_h1[r * 64 + jc] = sigf(gr[192]) * tanhfast(c);
        }
        __syncthreads();

        // ---------- fc: y = h1 @ Wfc^T + bfc ; write out + feed back ----------
        {
            float acc[8][4];
#pragma unroll
            for (int m = 0; m < 8; ++m)
#pragma unroll
                for (int j = 0; j < 4; ++j) acc[m][j] = bfcv[j];
            gemm128<64, 64>(acc, s_h1, g_Wfct, w, ln);

            // Output layout: [ y_last (B*D) | y_stack (NSTEP*B*D) ]
            float* ystack = out + (size_t)(1 + t) * ((size_t)B_SZ * D_SZ);
#pragma unroll
            for (int m = 0; m < 8; ++m) {
                int row = w * 8 + m;
                size_t go = (size_t)(rowg0 + row) * 128 + ln * 4;
                float4 v = make_float4(acc[m][0], acc[m][1], acc[m][2], acc[m][3]);
                *(float4*)(ystack + go) = v;
                *(float4*)(s_inp + row * 128 + ln * 4) = v;   // next-step input
                if (t == NSTEP - 1) *(float4*)(out + go) = v; // y_last
            }
        }
        __syncthreads();
    }
}

extern "C" void kernel_launch(void* const* d_in, const int* in_sizes, int n_in,
                              void* d_out, int out_size)
{
    (void)in_sizes; (void)n_in; (void)out_size;
    const float* x    = (const float*)d_in[0];
    const float* Wih0 = (const float*)d_in[1];
    const float* Whh0 = (const float*)d_in[2];
    const float* b0   = (const float*)d_in[3];
    const float* Wih1 = (const float*)d_in[4];
    const float* Whh1 = (const float*)d_in[5];
    const float* b1   = (const float*)d_in[6];
    const float* Wfc  = (const float*)d_in[7];
    const float* bfc  = (const float*)d_in[8];
    float* out = (float*)d_out;

    // Prologue: K-major weight layout (cheap, same stream -> ordered).
    transpose_weights<<<(192 * 256 + 128 * 256 + 64 * 128 + 255) / 256, 256>>>(
        Wih0, Whh0, Wih1, Whh1, Wfc);

    cudaFuncSetAttribute(lstm_kernel,
                         cudaFuncAttributeMaxDynamicSharedMemorySize,
                         SM_FLOATS * sizeof(float));
    lstm_kernel<<<NCTA, NTHR, SM_FLOATS * sizeof(float)>>>(x, b0, b1, bfc, out);
}

// round 7
// speedup vs baseline: 1.1085x; 1.1085x over previous
#include <cuda_runtime.h>

// Problem constants (shapes fixed by the reference).
#define B_SZ   32768
#define D_SZ   128
#define H_SZ   64
#define NSTEP  32
#define ROWS   64       // batch rows per CTA
#define NTHR   256
#define NCTA   (B_SZ / ROWS)   // 512

// Packed K-major weights (prologue-built, read-only after).
// Gate GEMM layout: W[k][256] where position p encodes
//   p < 128 : gates i,f  -> p = ln*4 + g*2 + j2      (g in {0,1})
//   p >=128 : gates g,o  -> p = 128 + ln*4 + (g-2)*2 + j2
// mapping to logical gate column c = 64*g + 2*ln + j2.
// Lane ln loads float4 at [k*256 + ln*4]     = (i0,i1,f0,f1) = 2 f32x2 pairs
//          and float4 at [k*256 + 128 + ln*4] = (g0,g1,o0,o1) = 2 f32x2 pairs
// both fully coalesced (512 B per warp per LDG.128).
__device__ __align__(16) float g_W0p[192 * 256];   // rows 0..127 Wih0^T, 128..191 Whh0^T
__device__ __align__(16) float g_W1p[128 * 256];   // rows 0..63  Wih1^T, 64..127  Whh1^T
__device__ __align__(16) float g_Wfct[64 * 128];   // plain Wfc^T (K-major)

__global__ void pack_weights(const float* __restrict__ Wih0,
                             const float* __restrict__ Whh0,
                             const float* __restrict__ Wih1,
                             const float* __restrict__ Whh1,
                             const float* __restrict__ Wfc)
{
    int i = blockIdx.x * blockDim.x + threadIdx.x;
    const int S0 = 192 * 256;
    const int S1 = S0 + 128 * 256;
    const int S2 = S1 + 64 * 128;
    if (i < S0) {
        int k = i >> 8, p = i & 255;
        int half = p >> 7, q = p & 127;
        int ln = q >> 2, g = half * 2 + ((q >> 1) & 1), j2 = q & 1;
        int c = 64 * g + 2 * ln + j2;
        g_W0p[i] = (k < 128) ? Wih0[c * 128 + k] : Whh0[c * 64 + (k - 128)];
    } else if (i < S1) {
        int ii = i - S0;
        int k = ii >> 8, p = ii & 255;
        int half = p >> 7, q = p & 127;
        int ln = q >> 2, g = half * 2 + ((q >> 1) & 1), j2 = q & 1;
        int c = 64 * g + 2 * ln + j2;
        g_W1p[ii] = (k < 64) ? Wih1[c * 64 + k] : Whh1[c * 64 + (k - 64)];
    } else if (i < S2) {
        int ii = i - S1;
        int k = ii >> 7, n = ii & 127;
        g_Wfct[ii] = Wfc[n * 64 + k];
    }
}

// ---- f32x2 helpers -------------------------------------------------------
typedef unsigned long long u64t;

__device__ __forceinline__ u64t pack2(float x, float y) {
    u64t r;
    asm("mov.b64 %0, {%1, %2};" : "=l"(r) : "f"(x), "f"(y));
    return r;
}
__device__ __forceinline__ u64t dup1(float x) {
    u64t r;
    asm("mov.b64 %0, {%1, %1};" : "=l"(r) : "f"(x));
    return r;
}
__device__ __forceinline__ void unpack2(u64t v, float& x, float& y) {
    asm("mov.b64 {%0, %1}, %2;" : "=f"(x), "=f"(y) : "l"(v));
}
__device__ __forceinline__ void ffma2(u64t& d, u64t a, u64t b) {
    asm("fma.rn.f32x2 %0, %1, %2, %0;" : "+l"(d) : "l"(a), "l"(b));
}

__device__ __forceinline__ float sigf(float x) {
    return __fdividef(1.0f, 1.0f + __expf(-x));
}
__device__ __forceinline__ float tanhfast(float x) {
    return __fdividef(2.0f, 1.0f + __expf(-2.0f * x)) - 1.0f;
}

// C[64 x 256] += A[64 x K] * Wp[K x 256] in the packed-gate layout.
// acc[m][g] is an f32x2 pair for gate g, cols 2ln/2ln+1, row w*8+m.
template <int K, int LDA>
__device__ __forceinline__ void gemm256f(u64t acc[8][4],
                                         const float* __restrict__ As,
                                         const float* __restrict__ Wp,
                                         int w, int ln)
{
#pragma unroll 2
    for (int kk = 0; kk < K; kk += 4) {
        float4 a[8];
#pragma unroll
        for (int m = 0; m < 8; ++m)
            a[m] = *(const float4*)(As + (w * 8 + m) * LDA + kk);
        ulonglong2 bif[4], bgo[4];
#pragma unroll
        for (int e = 0; e < 4; ++e) {
            bif[e] = *(const ulonglong2*)(Wp + (kk + e) * 256 + ln * 4);
            bgo[e] = *(const ulonglong2*)(Wp + (kk + e) * 256 + 128 + ln * 4);
        }
#pragma unroll
        for (int m = 0; m < 8; ++m) {
            float av[4] = {a[m].x, a[m].y, a[m].z, a[m].w};
#pragma unroll
            for (int e = 0; e < 4; ++e) {
                u64t ad = dup1(av[e]);
                ffma2(acc[m][0], ad, bif[e].x);
                ffma2(acc[m][1], ad, bif[e].y);
                ffma2(acc[m][2], ad, bgo[e].x);
                ffma2(acc[m][3], ad, bgo[e].y);
            }
        }
    }
}

// C[64 x 128] += A[64 x K] * Wt[K x 128] (fc). acc[m][h] pairs cols 4ln+2h..+1.
template <int K, int LDA>
__device__ __forceinline__ void gemm128f(u64t acc[8][2],
                                         const float* __restrict__ As,
                                         const float* __restrict__ Wt,
                                         int w, int ln)
{
#pragma unroll 2
    for (int kk = 0; kk < K; kk += 4) {
        float4 a[8];
#pragma unroll
        for (int m = 0; m < 8; ++m)
            a[m] = *(const float4*)(As + (w * 8 + m) * LDA + kk);
        ulonglong2 b[4];
#pragma unroll
        for (int e = 0; e < 4; ++e)
            b[e] = *(const ulonglong2*)(Wt + (kk + e) * 128 + ln * 4);
#pragma unroll
        for (int m = 0; m < 8; ++m) {
            float av[4] = {a[m].x, a[m].y, a[m].z, a[m].w};
#pragma unroll
            for (int e = 0; e < 4; ++e) {
                u64t ad = dup1(av[e]);
                ffma2(acc[m][0], ad, b[e].x);
                ffma2(acc[m][1], ad, b[e].y);
            }
        }
    }
}

// Fused LSTM cell epilogue: acc holds gate pairs (i,f,g,o); c is persistent
// per-thread cell state; h pair written straight to SMEM.
__device__ __forceinline__ void cell_update(u64t acc[8][4], float2 c[8],
                                            float* __restrict__ hdst,
                                            int w, int ln)
{
#pragma unroll
    for (int m = 0; m < 8; ++m) {
        float ix, iy, fx, fy, gx, gy, ox, oy;
        unpack2(acc[m][0], ix, iy);
        unpack2(acc[m][1], fx, fy);
        unpack2(acc[m][2], gx, gy);
        unpack2(acc[m][3], ox, oy);
        float cx = sigf(fx) * c[m].x + sigf(ix) * tanhfast(gx);
        float cy = sigf(fy) * c[m].y + sigf(iy) * tanhfast(gy);
        c[m].x = cx; c[m].y = cy;
        *(float2*)(hdst + (w * 8 + m) * 64 + 2 * ln) =
            make_float2(sigf(ox) * tanhfast(cx), sigf(oy) * tanhfast(cy));
    }
}

// SMEM (floats): inp[64*128] | h0[64*64] | h1[64*64]  = 16384 floats = 64 KB
#define SM_INP 0
#define SM_H0  (64 * 128)
#define SM_H1  (SM_H0 + 64 * 64)
#define SM_FLOATS (SM_H1 + 64 * 64)

__global__ __launch_bounds__(NTHR) void lstm_kernel(
    const float* __restrict__ x,
    const float* __restrict__ b0,
    const float* __restrict__ b1,
    const float* __restrict__ bfc,
    float* __restrict__ out)
{
    extern __shared__ float sm[];
    float* s_inp = sm + SM_INP;
    float* s_h0  = sm + SM_H0;
    float* s_h1  = sm + SM_H1;

    const int tid = threadIdx.x;
    const int w   = tid >> 5;
    const int ln  = tid & 31;
    const int rowg0 = blockIdx.x * ROWS;

    // Stage x tile (coalesced float4).
#pragma unroll 1
    for (int idx = tid; idx < 64 * 32; idx += NTHR) {
        int r = idx >> 5, cc = (idx & 31) << 2;
        *(float4*)(s_inp + r * 128 + cc) =
            *(const float4*)(x + (size_t)(rowg0 + r) * 128 + cc);
    }
#pragma unroll 1
    for (int idx = tid; idx < 64 * 64; idx += NTHR) {
        s_h0[idx] = 0.0f;
        s_h1[idx] = 0.0f;
    }

    // Bias pairs matching gate ownership (cols 2ln, 2ln+1 of gate g).
    u64t b0p[4], b1p[4], bfcp[2];
#pragma unroll
    for (int g = 0; g < 4; ++g) {
        float2 t0 = *(const float2*)(b0 + 64 * g + 2 * ln);
        float2 t1 = *(const float2*)(b1 + 64 * g + 2 * ln);
        b0p[g] = pack2(t0.x, t0.y);
        b1p[g] = pack2(t1.x, t1.y);
    }
    {
        float4 t = *(const float4*)(bfc + ln * 4);
        bfcp[0] = pack2(t.x, t.y);
        bfcp[1] = pack2(t.z, t.w);
    }

    // Persistent cell state: rows w*8..w*8+7, cols 2ln, 2ln+1.
    float2 c0[8], c1[8];
#pragma unroll
    for (int m = 0; m < 8; ++m) {
        c0[m] = make_float2(0.0f, 0.0f);
        c1[m] = make_float2(0.0f, 0.0f);
    }

    __syncthreads();

#pragma unroll 1
    for (int t = 0; t < NSTEP; ++t) {
        // ---- layer 0 gates ----
        {
            u64t acc[8][4];
#pragma unroll
            for (int m = 0; m < 8; ++m)
#pragma unroll
                for (int g = 0; g < 4; ++g) acc[m][g] = b0p[g];
            gemm256f<128, 128>(acc, s_inp, g_W0p, w, ln);
            gemm256f<64, 64>(acc, s_h0, g_W0p + 128 * 256, w, ln);
            __syncthreads();                 // all h0 reads done
            cell_update(acc, c0, s_h0, w, ln);
        }
        __syncthreads();

        // ---- layer 1 gates ----
        {
            u64t acc[8][4];
#pragma unroll
            for (int m = 0; m < 8; ++m)
#pragma unroll
                for (int g = 0; g < 4; ++g) acc[m][g] = b1p[g];
            gemm256f<64, 64>(acc, s_h0, g_W1p, w, ln);
            gemm256f<64, 64>(acc, s_h1, g_W1p + 64 * 256, w, ln);
            __syncthreads();                 // all h1 reads done
            cell_update(acc, c1, s_h1, w, ln);
        }
        __syncthreads();

        // ---- fc: y = h1 @ Wfc^T + bfc ; emit + feed back ----
        {
            u64t acc2[8][2];
#pragma unroll
            for (int m = 0; m < 8; ++m) {
                acc2[m][0] = bfcp[0];
                acc2[m][1] = bfcp[1];
            }
            gemm128f<64, 64>(acc2, s_h1, g_Wfct, w, ln);

            float* ystack = out + (size_t)(1 + t) * ((size_t)B_SZ * D_SZ);
#pragma unroll
            for (int m = 0; m < 8; ++m) {
                int row = w * 8 + m;
                float y0, y1, y2, y3;
                unpack2(acc2[m][0], y0, y1);
                unpack2(acc2[m][1], y2, y3);
                float4 v = make_float4(y0, y1, y2, y3);
                size_t go = (size_t)(rowg0 + row) * 128 + ln * 4;
                *(float4*)(ystack + go) = v;
                *(float4*)(s_inp + row * 128 + ln * 4) = v;   // next input
                if (t == NSTEP - 1) *(float4*)(out + go) = v; // y_last
            }
        }
        __syncthreads();
    }
}

extern "C" void kernel_launch(void* const* d_in, const int* in_sizes, int n_in,
                              void* d_out, int out_size)
{
    (void)in_sizes; (void)n_in; (void)out_size;
    const float* x    = (const float*)d_in[0];
    const float* Wih0 = (const float*)d_in[1];
    const float* Whh0 = (const float*)d_in[2];
    const float* b0   = (const float*)d_in[3];
    const float* Wih1 = (const float*)d_in[4];
    const float* Whh1 = (const float*)d_in[5];
    const float* b1   = (const float*)d_in[6];
    const float* Wfc  = (const float*)d_in[7];
    const float* bfc  = (const float*)d_in[8];
    float* out = (float*)d_out;

    pack_weights<<<(192 * 256 + 128 * 256 + 64 * 128 + 255) / 256, 256>>>(
        Wih0, Whh0, Wih1, Whh1, Wfc);

    cudaFuncSetAttribute(lstm_kernel,
                         cudaFuncAttributeMaxDynamicSharedMemorySize,
                         SM_FLOATS * sizeof(float));
    lstm_kernel<<<NCTA, NTHR, SM_FLOATS * sizeof(float)>>>(x, b0, b1, bfc, out);
}

// round 9
// speedup vs baseline: 1.4967x; 1.3502x over previous
#include <cuda_runtime.h>

// Problem constants (shapes fixed by the reference).
#define B_SZ   32768
#define D_SZ   128
#define H_SZ   64
#define NSTEP  32
#define ROWS   32       // batch rows per CTA
#define NTHR   256
#define NCTA   (B_SZ / ROWS)   // 1024

// Packed K-major weights (prologue-built, read-only after).
// Gate GEMM layout: W[k][256] where position p encodes
//   p < 128 : gates i,f  -> p = ln*4 + g*2 + j2      (g in {0,1})
//   p >=128 : gates g,o  -> p = 128 + ln*4 + (g-2)*2 + j2
// mapping to logical gate column c = 64*g + 2*ln + j2.
// Lane ln loads float4 at [k*256 + ln*4]      = (i0,i1,f0,f1) = 2 f32x2 pairs
//          and float4 at [k*256 + 128 + ln*4] = (g0,g1,o0,o1) = 2 f32x2 pairs
// both fully coalesced (512 B per warp per LDG.128).
__device__ __align__(16) float g_W0p[192 * 256];   // rows 0..127 Wih0^T, 128..191 Whh0^T
__device__ __align__(16) float g_W1p[128 * 256];   // rows 0..63  Wih1^T, 64..127  Whh1^T
__device__ __align__(16) float g_Wfct[64 * 128];   // plain Wfc^T (K-major)

__global__ void pack_weights(const float* __restrict__ Wih0,
                             const float* __restrict__ Whh0,
                             const float* __restrict__ Wih1,
                             const float* __restrict__ Whh1,
                             const float* __restrict__ Wfc)
{
    int i = blockIdx.x * blockDim.x + threadIdx.x;
    const int S0 = 192 * 256;
    const int S1 = S0 + 128 * 256;
    const int S2 = S1 + 64 * 128;
    if (i < S0) {
        int k = i >> 8, p = i & 255;
        int half = p >> 7, q = p & 127;
        int ln = q >> 2, g = half * 2 + ((q >> 1) & 1), j2 = q & 1;
        int c = 64 * g + 2 * ln + j2;
        g_W0p[i] = (k < 128) ? Wih0[c * 128 + k] : Whh0[c * 64 + (k - 128)];
    } else if (i < S1) {
        int ii = i - S0;
        int k = ii >> 8, p = ii & 255;
        int half = p >> 7, q = p & 127;
        int ln = q >> 2, g = half * 2 + ((q >> 1) & 1), j2 = q & 1;
        int c = 64 * g + 2 * ln + j2;
        g_W1p[ii] = (k < 64) ? Wih1[c * 64 + k] : Whh1[c * 64 + (k - 64)];
    } else if (i < S2) {
        int ii = i - S1;
        int k = ii >> 7, n = ii & 127;
        g_Wfct[ii] = Wfc[n * 64 + k];
    }
}

// ---- f32x2 helpers -------------------------------------------------------
typedef unsigned long long u64t;

__device__ __forceinline__ u64t pack2(float x, float y) {
    u64t r;
    asm("mov.b64 %0, {%1, %2};" : "=l"(r) : "f"(x), "f"(y));
    return r;
}
__device__ __forceinline__ u64t dup1(float x) {
    u64t r;
    asm("mov.b64 %0, {%1, %1};" : "=l"(r) : "f"(x));
    return r;
}
__device__ __forceinline__ void unpack2(u64t v, float& x, float& y) {
    asm("mov.b64 {%0, %1}, %2;" : "=f"(x), "=f"(y) : "l"(v));
}
__device__ __forceinline__ void ffma2(u64t& d, u64t a, u64t b) {
    asm("fma.rn.f32x2 %0, %1, %2, %0;" : "+l"(d) : "l"(a), "l"(b));
}

__device__ __forceinline__ float sigf(float x) {
    return __fdividef(1.0f, 1.0f + __expf(-x));
}
__device__ __forceinline__ float tanhfast(float x) {
    return __fdividef(2.0f, 1.0f + __expf(-2.0f * x)) - 1.0f;
}

// C[32 x 256] += A[32 x K] * Wp[K x 256] in the packed-gate layout.
// Warp w owns rows w*4..w*4+3; lane ln owns cols 2ln/2ln+1 of each gate.
// acc[m][g] is an f32x2 pair for gate g, row w*4+m.
template <int K, int LDA>
__device__ __forceinline__ void gemm256f(u64t acc[4][4],
                                         const float* __restrict__ As,
                                         const float* __restrict__ Wp,
                                         int w, int ln)
{
#pragma unroll 2
    for (int kk = 0; kk < K; kk += 4) {
        float4 a[4];
#pragma unroll
        for (int m = 0; m < 4; ++m)
            a[m] = *(const float4*)(As + (w * 4 + m) * LDA + kk);
#pragma unroll
        for (int e = 0; e < 4; ++e) {
            ulonglong2 bif = *(const ulonglong2*)(Wp + (kk + e) * 256 + ln * 4);
            ulonglong2 bgo = *(const ulonglong2*)(Wp + (kk + e) * 256 + 128 + ln * 4);
            float av[4] = {e == 0 ? a[0].x : e == 1 ? a[0].y : e == 2 ? a[0].z : a[0].w,
                           e == 0 ? a[1].x : e == 1 ? a[1].y : e == 2 ? a[1].z : a[1].w,
                           e == 0 ? a[2].x : e == 1 ? a[2].y : e == 2 ? a[2].z : a[2].w,
                           e == 0 ? a[3].x : e == 1 ? a[3].y : e == 2 ? a[3].z : a[3].w};
#pragma unroll
            for (int m = 0; m < 4; ++m) {
                u64t ad = dup1(av[m]);
                ffma2(acc[m][0], ad, bif.x);
                ffma2(acc[m][1], ad, bif.y);
                ffma2(acc[m][2], ad, bgo.x);
                ffma2(acc[m][3], ad, bgo.y);
            }
        }
    }
}

// C[32 x 128] += A[32 x K] * Wt[K x 128] (fc). acc[m][h] pairs cols 4ln+2h..+1.
template <int K, int LDA>
__device__ __forceinline__ void gemm128f(u64t acc[4][2],
                                         const float* __restrict__ As,
                                         const float* __restrict__ Wt,
                                         int w, int ln)
{
#pragma unroll 2
    for (int kk = 0; kk < K; kk += 4) {
        float4 a[4];
#pragma unroll
        for (int m = 0; m < 4; ++m)
            a[m] = *(const float4*)(As + (w * 4 + m) * LDA + kk);
#pragma unroll
        for (int e = 0; e < 4; ++e) {
            ulonglong2 b = *(const ulonglong2*)(Wt + (kk + e) * 128 + ln * 4);
            float av[4] = {e == 0 ? a[0].x : e == 1 ? a[0].y : e == 2 ? a[0].z : a[0].w,
                           e == 0 ? a[1].x : e == 1 ? a[1].y : e == 2 ? a[1].z : a[1].w,
                           e == 0 ? a[2].x : e == 1 ? a[2].y : e == 2 ? a[2].z : a[2].w,
                           e == 0 ? a[3].x : e == 1 ? a[3].y : e == 2 ? a[3].z : a[3].w};
#pragma unroll
            for (int m = 0; m < 4; ++m) {
                u64t ad = dup1(av[m]);
                ffma2(acc[m][0], ad, b.x);
                ffma2(acc[m][1], ad, b.y);
            }
        }
    }
}

// Fused LSTM cell epilogue: acc holds gate pairs (i,f,g,o); c is persistent
// per-thread cell state; h pair written straight to SMEM.
__device__ __forceinline__ void cell_update(u64t acc[4][4], float2 c[4],
                                            float* __restrict__ hdst,
                                            int w, int ln)
{
#pragma unroll
    for (int m = 0; m < 4; ++m) {
        float ix, iy, fx, fy, gx, gy, ox, oy;
        unpack2(acc[m][0], ix, iy);
        unpack2(acc[m][1], fx, fy);
        unpack2(acc[m][2], gx, gy);
        unpack2(acc[m][3], ox, oy);
        float cx = sigf(fx) * c[m].x + sigf(ix) * tanhfast(gx);
        float cy = sigf(fy) * c[m].y + sigf(iy) * tanhfast(gy);
        c[m].x = cx; c[m].y = cy;
        *(float2*)(hdst + (w * 4 + m) * 64 + 2 * ln) =
            make_float2(sigf(ox) * tanhfast(cx), sigf(oy) * tanhfast(cy));
    }
}

// SMEM (floats): inp[32*128] | h0[32*64] | h1[32*64]  = 8192 floats = 32 KB
#define SM_INP 0
#define SM_H0  (32 * 128)
#define SM_H1  (SM_H0 + 32 * 64)
#define SM_FLOATS (SM_H1 + 32 * 64)

__global__ __launch_bounds__(NTHR, 2) void lstm_kernel(
    const float* __restrict__ x,
    const float* __restrict__ b0,
    const float* __restrict__ b1,
    const float* __restrict__ bfc,
    float* __restrict__ out)
{
    extern __shared__ float sm[];
    float* s_inp = sm + SM_INP;
    float* s_h0  = sm + SM_H0;
    float* s_h1  = sm + SM_H1;

    const int tid = threadIdx.x;
    const int w   = tid >> 5;
    const int ln  = tid & 31;
    const int rowg0 = blockIdx.x * ROWS;

    // Stage x tile (coalesced float4): 32 rows x 128 cols = 1024 float4.
#pragma unroll 1
    for (int idx = tid; idx < 32 * 32; idx += NTHR) {
        int r = idx >> 5, cc = (idx & 31) << 2;
        *(float4*)(s_inp + r * 128 + cc) =
            *(const float4*)(x + (size_t)(rowg0 + r) * 128 + cc);
    }
#pragma unroll 1
    for (int idx = tid; idx < 32 * 64; idx += NTHR) {
        s_h0[idx] = 0.0f;
        s_h1[idx] = 0.0f;
    }

    // Bias pairs matching gate ownership (cols 2ln, 2ln+1 of gate g).
    u64t b0p[4], b1p[4], bfcp[2];
#pragma unroll
    for (int g = 0; g < 4; ++g) {
        float2 t0 = *(const float2*)(b0 + 64 * g + 2 * ln);
        float2 t1 = *(const float2*)(b1 + 64 * g + 2 * ln);
        b0p[g] = pack2(t0.x, t0.y);
        b1p[g] = pack2(t1.x, t1.y);
    }
    {
        float4 t = *(const float4*)(bfc + ln * 4);
        bfcp[0] = pack2(t.x, t.y);
        bfcp[1] = pack2(t.z, t.w);
    }

    // Persistent cell state: rows w*4..w*4+3, cols 2ln, 2ln+1.
    float2 c0[4], c1[4];
#pragma unroll
    for (int m = 0; m < 4; ++m) {
        c0[m] = make_float2(0.0f, 0.0f);
        c1[m] = make_float2(0.0f, 0.0f);
    }

    __syncthreads();

#pragma unroll 1
    for (int t = 0; t < NSTEP; ++t) {
        // ---- layer 0 gates ----
        {
            u64t acc[4][4];
#pragma unroll
            for (int m = 0; m < 4; ++m)
#pragma unroll
                for (int g = 0; g < 4; ++g) acc[m][g] = b0p[g];
            gemm256f<128, 128>(acc, s_inp, g_W0p, w, ln);
            gemm256f<64, 64>(acc, s_h0, g_W0p + 128 * 256, w, ln);
            __syncthreads();                 // all h0 reads done
            cell_update(acc, c0, s_h0, w, ln);
        }
        __syncthreads();

        // ---- layer 1 gates ----
        {
            u64t acc[4][4];
#pragma unroll
            for (int m = 0; m < 4; ++m)
#pragma unroll
                for (int g = 0; g < 4; ++g) acc[m][g] = b1p[g];
            gemm256f<64, 64>(acc, s_h0, g_W1p, w, ln);
            gemm256f<64, 64>(acc, s_h1, g_W1p + 64 * 256, w, ln);
            __syncthreads();                 // all h1 reads done
            cell_update(acc, c1, s_h1, w, ln);
        }
        __syncthreads();

        // ---- fc: y = h1 @ Wfc^T + bfc ; emit + feed back ----
        {
            u64t acc2[4][2];
#pragma unroll
            for (int m = 0; m < 4; ++m) {
                acc2[m][0] = bfcp[0];
                acc2[m][1] = bfcp[1];
            }
            gemm128f<64, 64>(acc2, s_h1, g_Wfct, w, ln);

            float* ystack = out + (size_t)(1 + t) * ((size_t)B_SZ * D_SZ);
#pragma unroll
            for (int m = 0; m < 4; ++m) {
                int row = w * 4 + m;
                float y0, y1, y2, y3;
                unpack2(acc2[m][0], y0, y1);
                unpack2(acc2[m][1], y2, y3);
                float4 v = make_float4(y0, y1, y2, y3);
                size_t go = (size_t)(rowg0 + row) * 128 + ln * 4;
                *(float4*)(ystack + go) = v;
                *(float4*)(s_inp + row * 128 + ln * 4) = v;   // next input
                if (t == NSTEP - 1) *(float4*)(out + go) = v; // y_last
            }
        }
        __syncthreads();
    }
}

extern "C" void kernel_launch(void* const* d_in, const int* in_sizes, int n_in,
                              void* d_out, int out_size)
{
    (void)in_sizes; (void)n_in; (void)out_size;
    const float* x    = (const float*)d_in[0];
    const float* Wih0 = (const float*)d_in[1];
    const float* Whh0 = (const float*)d_in[2];
    const float* b0   = (const float*)d_in[3];
    const float* Wih1 = (const float*)d_in[4];
    const float* Whh1 = (const float*)d_in[5];
    const float* b1   = (const float*)d_in[6];
    const float* Wfc  = (const float*)d_in[7];
    const float* bfc  = (const float*)d_in[8];
    float* out = (float*)d_out;

    pack_weights<<<(192 * 256 + 128 * 256 + 64 * 128 + 255) / 256, 256>>>(
        Wih0, Whh0, Wih1, Whh1, Wfc);

    cudaFuncSetAttribute(lstm_kernel,
                         cudaFuncAttributeMaxDynamicSharedMemorySize,
                         SM_FLOATS * sizeof(float));
    lstm_kernel<<<NCTA, NTHR, SM_FLOATS * sizeof(float)>>>(x, b0, b1, bfc, out);
}